// round 4
// baseline (speedup 1.0000x reference)
#include <cuda_runtime.h>
#include <cstdint>

// Segment-sum: out[src[e], f] += edge_w[e, f], F=16 (f32).
// Persistent grid-stride kernel, software-pipelined: loads for batch i+1 are
// issued before REDs for batch i, so each warp continuously co-feeds the LSU
// with streaming loads and scattered reductions.
// Item = (edge, quad): 4 consecutive lanes cover one 64B output row, so the
// coalescer merges each row's 4x16B REDs into one wavefront group.

static constexpr int F = 16;
static constexpr int THREADS = 256;
static constexpr int BLOCKS = 148 * 8;   // fill the chip exactly

__device__ __forceinline__ void red_v4(float* dst, float4 w) {
    asm volatile("red.global.add.v4.f32 [%0], {%1, %2, %3, %4};"
                 :: "l"(dst), "f"(w.x), "f"(w.y), "f"(w.z), "f"(w.w)
                 : "memory");
}

__global__ void __launch_bounds__(THREADS) scatter_add_kernel(
        const int* __restrict__ src,
        const float4* __restrict__ w4,
        float* __restrict__ out,
        int total) {                       // total = E*4 quad-items
    const int G = THREADS * BLOCKS;        // items per sweep
    int i = blockIdx.x * THREADS + threadIdx.x;

    // ---- prologue: load batch 0 ----
    int   s_cur = 0;
    float4 w_cur = make_float4(0.f, 0.f, 0.f, 0.f);
    bool  v_cur = (i < total);
    if (v_cur) {
        s_cur = __ldg(&src[i >> 2]);
        w_cur = __ldcs(&w4[i]);
    }

    int i_cur = i;
    i += G;

    // ---- steady state: prefetch i, reduce i_cur ----
    while (i < total) {
        const int   s_nxt = __ldg(&src[i >> 2]);
        const float4 w_nxt = __ldcs(&w4[i]);

        red_v4(out + (size_t)s_cur * F + (i_cur & 3) * 4, w_cur);

        s_cur = s_nxt; w_cur = w_nxt; i_cur = i;
        i += G;
    }

    // ---- epilogue ----
    if (v_cur)
        red_v4(out + (size_t)s_cur * F + (i_cur & 3) * 4, w_cur);
}

extern "C" void kernel_launch(void* const* d_in, const int* in_sizes, int n_in,
                              void* d_out, int out_size) {
    const int* edge  = (const int*)d_in[0];        // [2, E]; row 0 = src
    const float4* w4 = (const float4*)d_in[1];     // [E, 16] f32 == [E*4] float4
    float* out       = (float*)d_out;              // [N, 16] f32

    const int E = in_sizes[1] / F;                 // 3,200,000
    const int total = E * 4;                       // 12.8M quad-items

    // 1) zero the poisoned output via the HW memset path (graph-capturable)
    cudaMemsetAsync(d_out, 0, (size_t)out_size * sizeof(float));

    // 2) persistent pipelined scatter-add
    scatter_add_kernel<<<BLOCKS, THREADS>>>(edge, w4, out, total);
}